// round 2
// baseline (speedup 1.0000x reference)
#include <cuda_runtime.h>

// Row-wise normalization: out[r, :] = in[r, :] / sum(in[r, :])
// Rows = 2*32*1024 = 65536, row length = 1024 floats = 256 float4.
// One block per row, 256 threads, one float4 per thread held in registers
// so each element is read exactly once from HBM and written exactly once.
__global__ void __launch_bounds__(256, 8)
normalizer_kernel(const float4* __restrict__ in, float4* __restrict__ out) {
    const unsigned row  = blockIdx.x;
    const unsigned base = row * 256u + threadIdx.x;

    float4 v = in[base];

    // Per-thread partial sum
    float s = (v.x + v.y) + (v.z + v.w);

    // Warp reduction
    #pragma unroll
    for (int off = 16; off > 0; off >>= 1)
        s += __shfl_xor_sync(0xffffffffu, s, off);

    // Cross-warp reduction via 8-word shared broadcast
    __shared__ float warp_sums[8];
    const unsigned wid = threadIdx.x >> 5;
    const unsigned lid = threadIdx.x & 31u;
    if (lid == 0) warp_sums[wid] = s;
    __syncthreads();

    float deg = (warp_sums[0] + warp_sums[1]) + (warp_sums[2] + warp_sums[3])
              + (warp_sums[4] + warp_sums[5]) + (warp_sums[6] + warp_sums[7]);

    float inv = 1.0f / deg;
    if (!isfinite(inv)) inv = 0.0f;   // reference: remove_nan_inf on 1/degree

    v.x *= inv; v.y *= inv; v.z *= inv; v.w *= inv;
    out[base] = v;
}

extern "C" void kernel_launch(void* const* d_in, const int* in_sizes, int n_in,
                              void* d_out, int out_size) {
    (void)in_sizes; (void)n_in; (void)out_size;
    const float4* in  = (const float4*)d_in[0];
    float4*       out = (float4*)d_out;

    // 2 * 32 * 1024 rows of 1024 floats
    const unsigned n_rows = 2u * 32u * 1024u;
    normalizer_kernel<<<n_rows, 256>>>(in, out);
}

// round 3
// speedup vs baseline: 1.0691x; 1.0691x over previous
#include <cuda_runtime.h>

// Row-wise normalization: out[r, :] = in[r, :] / sum(in[r, :])
// Rows = 2*32*1024 = 65536, row length = 1024 floats = 256 float4.
//
// One WARP per row: 32 lanes x 8 coalesced float4 loads, held in registers.
// - no __syncthreads, no shared memory (warp-shuffle reduction only)
// - MLP = 8 front-batched LDG.128 per thread for latency hiding
// - .cs streaming hints: 537 MB stream has no reuse, skip L2 retention
__global__ void __launch_bounds__(256, 4)
normalizer_kernel(const float4* __restrict__ in, float4* __restrict__ out) {
    const unsigned row  = blockIdx.x * 8u + (threadIdx.x >> 5);
    const unsigned lane = threadIdx.x & 31u;

    const float4* __restrict__ rp = in  + (size_t)row * 256u + lane;
    float4*       __restrict__ wp = out + (size_t)row * 256u + lane;

    float4 v[8];
    #pragma unroll
    for (int k = 0; k < 8; k++)
        v[k] = __ldcs(rp + 32 * k);          // 8 independent LDG.128, streaming

    float s = 0.0f;
    #pragma unroll
    for (int k = 0; k < 8; k++)
        s += (v[k].x + v[k].y) + (v[k].z + v[k].w);

    // Warp reduction — the whole row lives in this warp
    #pragma unroll
    for (int off = 16; off > 0; off >>= 1)
        s += __shfl_xor_sync(0xffffffffu, s, off);

    float inv = 1.0f / s;
    if (!isfinite(inv)) inv = 0.0f;          // reference: remove_nan_inf on 1/degree

    #pragma unroll
    for (int k = 0; k < 8; k++) {
        v[k].x *= inv; v[k].y *= inv; v[k].z *= inv; v[k].w *= inv;
        __stcs(wp + 32 * k, v[k]);           // streaming store
    }
}

extern "C" void kernel_launch(void* const* d_in, const int* in_sizes, int n_in,
                              void* d_out, int out_size) {
    (void)in_sizes; (void)n_in; (void)out_size;
    const float4* in  = (const float4*)d_in[0];
    float4*       out = (float4*)d_out;

    // 65536 rows, 8 rows (warps) per block -> 8192 blocks
    normalizer_kernel<<<65536 / 8, 256>>>(in, out);
}